// round 1
// baseline (speedup 1.0000x reference)
#include <cuda_runtime.h>
#include <cstdint>

// ---------------------------------------------------------------------------
// 3x conv3x3 chain, fp32, NCHW, stride 1 pad 1.
// N=16, H=W=224. 64 -> 128 -> 128 -> 64 channels.
//
// Strategy: direct convolution, shared-memory tiled, built entirely around
// packed fp32x2 FMA (fma.rn.f32x2 -> FFMA2 in SASS, 2x the FFMA issue rate).
//  - Block: 128 threads = 16 (w-pair) x 8 (row groups).
//  - Output tile per block: 32h x 32w x 8 output channels.
//  - Per thread: 8 co x 4 rows x 2 cols (pixel pair along W) = 64 outputs,
//    accumulators held as 32 packed b64 registers.
//  - Input tile in smem twice: copy A (natural) and copy B (shifted by one
//    float) so every (row, kw) tap is an aligned LDS.64 pixel-pair.
//  - Weights in smem pre-duplicated (w,w) so one broadcast LDS.64 feeds FMA2.
// ---------------------------------------------------------------------------

#define TILE      32
#define CI_TILE   4
#define HALO      34            // TILE + 2
#define HALO2     (HALO * HALO) // 1156
#define NBATCH    16
#define HW        224
#define CO_TILE   8

// Scratch intermediates: 16 * 128 * 224 * 224 floats each (411 MB).
__device__ float g_buf1[102760448];
__device__ float g_buf2[102760448];

__device__ __forceinline__ void fma2(unsigned long long& d,
                                     unsigned long long a,
                                     unsigned long long b)
{
    // packed 2xfp32 fused multiply-add: d.lo += a.lo*b.lo ; d.hi += a.hi*b.hi
    asm("fma.rn.f32x2 %0, %1, %2, %0;" : "+l"(d) : "l"(a), "l"(b));
}

template <int CIN>
__global__ __launch_bounds__(128, 4)
void conv3x3_f32x2_kernel(const float* __restrict__ in,
                          const float* __restrict__ wgt,
                          float* __restrict__ out,
                          int Cout)
{
    __shared__ __align__(16) float  sA[CI_TILE][HALO2];  // natural copy
    __shared__ __align__(16) float  sB[CI_TILE][HALO2];  // shifted-by-one copy: sB[j] = v[j+1]
    __shared__ __align__(16) float2 sW[CO_TILE][CI_TILE][9]; // duplicated weights

    const int tid = threadIdx.x;
    const int tx  = tid & 15;       // 16 w-pairs -> 32 output columns
    const int ty  = tid >> 4;       // 8 row groups
    const int cog = blockIdx.x;     // output-channel group (fastest -> L2 reuse of input tile)
    const int bh  = blockIdx.y / 7;
    const int bw  = blockIdx.y - bh * 7;
    const int n   = blockIdx.z;

    const int hb = bh * TILE;
    const int wb = bw * TILE;
    const int c0 = 2 * tx;          // halo col base of this thread's pixel pair (even)
    const int r0 = 4 * ty;          // output row base (also halo row base for kh=0,r2=0)

    unsigned long long acc[CO_TILE][4];
#pragma unroll
    for (int co = 0; co < CO_TILE; co++)
#pragma unroll
        for (int r = 0; r < 4; r++)
            acc[co][r] = 0ull;      // bits of (0.0f, 0.0f)

    for (int ci0 = 0; ci0 < CIN; ci0 += CI_TILE) {
        __syncthreads();   // protect smem from previous iteration's readers

        // ---- load input halo tile (CI_TILE channels), write both copies ----
        for (int idx = tid; idx < CI_TILE * HALO2; idx += 128) {
            int ciL = idx / HALO2;
            int rem = idx - ciL * HALO2;
            int r   = rem / HALO;
            int c   = rem - r * HALO;
            int gh  = hb - 1 + r;
            int gw  = wb - 1 + c;
            float v = 0.0f;
            if ((unsigned)gh < (unsigned)HW && (unsigned)gw < (unsigned)HW)
                v = in[((n * CIN + ci0 + ciL) * HW + gh) * HW + gw];
            sA[ciL][rem] = v;
            if (c > 0) sB[ciL][rem - 1] = v;   // sB[row][c-1] = v[c]
        }

        // ---- load weights, duplicated into both lanes of a float2 ----
        for (int idx = tid; idx < CO_TILE * CI_TILE * 9; idx += 128) {
            int co  = idx / (CI_TILE * 9);
            int rem = idx - co * (CI_TILE * 9);
            int ciL = rem / 9;
            int k   = rem - ciL * 9;
            float wv = wgt[((cog * CO_TILE + co) * CIN + ci0 + ciL) * 9 + k];
            sW[co][ciL][k] = make_float2(wv, wv);
        }
        __syncthreads();

        // ---- compute ----
#pragma unroll 1
        for (int ciL = 0; ciL < CI_TILE; ciL++) {
            // 6 halo rows x 3 kw taps, each an aligned 64-bit pixel pair
            unsigned long long inp[6][3];
#pragma unroll
            for (int r = 0; r < 6; r++) {
                const float* pa = &sA[ciL][(r0 + r) * HALO];
                const float* pb = &sB[ciL][(r0 + r) * HALO];
                inp[r][0] = *reinterpret_cast<const unsigned long long*>(pa + c0);     // cols (ow,   ow+1)
                inp[r][1] = *reinterpret_cast<const unsigned long long*>(pb + c0);     // cols (ow+1, ow+2)
                inp[r][2] = *reinterpret_cast<const unsigned long long*>(pa + c0 + 2); // cols (ow+2, ow+3)
            }
#pragma unroll
            for (int co = 0; co < CO_TILE; co++) {
#pragma unroll
                for (int kh = 0; kh < 3; kh++) {
#pragma unroll
                    for (int kw = 0; kw < 3; kw++) {
                        unsigned long long wp =
                            *reinterpret_cast<const unsigned long long*>(&sW[co][ciL][kh * 3 + kw]);
#pragma unroll
                        for (int r2 = 0; r2 < 4; r2++)
                            fma2(acc[co][r2], inp[r2 + kh][kw], wp);
                    }
                }
            }
        }
    }

    // ---- store: 64-bit stores of adjacent-column pairs ----
#pragma unroll
    for (int co = 0; co < CO_TILE; co++) {
#pragma unroll
        for (int r2 = 0; r2 < 4; r2++) {
            int h = hb + r0 + r2;
            float* p = &out[((n * Cout + cog * CO_TILE + co) * HW + h) * HW + wb + c0];
            *reinterpret_cast<unsigned long long*>(p) = acc[co][r2];
        }
    }
}

extern "C" void kernel_launch(void* const* d_in, const int* in_sizes, int n_in,
                              void* d_out, int out_size)
{
    const float* x  = (const float*)d_in[0];
    const float* w1 = (const float*)d_in[1];
    const float* w2 = (const float*)d_in[2];
    const float* w3 = (const float*)d_in[3];
    float* out = (float*)d_out;

    float* buf1 = nullptr;
    float* buf2 = nullptr;
    cudaGetSymbolAddress((void**)&buf1, g_buf1);
    cudaGetSymbolAddress((void**)&buf2, g_buf2);

    dim3 block(128);
    // conv1: 64 -> 128
    dim3 grid1(128 / CO_TILE, 7 * 7, NBATCH);
    conv3x3_f32x2_kernel<64><<<grid1, block>>>(x, w1, buf1, 128);
    // conv2: 128 -> 128
    dim3 grid2(128 / CO_TILE, 7 * 7, NBATCH);
    conv3x3_f32x2_kernel<128><<<grid2, block>>>(buf1, w2, buf2, 128);
    // conv3: 128 -> 64
    dim3 grid3(64 / CO_TILE, 7 * 7, NBATCH);
    conv3x3_f32x2_kernel<128><<<grid3, block>>>(buf2, w3, out, 64);
}

// round 2
// speedup vs baseline: 1.4394x; 1.4394x over previous
#include <cuda_runtime.h>

// ---------------------------------------------------------------------------
// 3x conv3x3 chain, fp32, NCHW, stride 1 pad 1. N=16, H=W=224, 64->128->128->64.
//
// Round 2: software-pipelined direct conv around packed fp32x2 FMA.
//  - Double-buffered smem (CI_TILE=2 channels per stage, 2 stages, ~39 KB).
//  - Register-staged prefetch: all next-stage LDGs issued BEFORE computing the
//    current stage; STS after barrier. DRAM latency hidden under 1152 cycles
//    of FMA2 work.
//  - Per-slot global offsets (bounds folded in as -1) computed ONCE before the
//    main loop -> no divisions / bounds math in the hot loop.
//  - Dual smem copies (natural + shifted-by-one) keep every 3x3 tap an aligned
//    LDS.64 pixel pair; weights duplicated (w,w) for broadcast LDS.64.
//  - Per thread: 8 co x 4 rows x 2 cols = 64 outputs in 32 packed accumulators.
// ---------------------------------------------------------------------------

#define TILE      32
#define CI_TILE   2
#define HALO      34
#define HALO2     1156
#define NELEM     (CI_TILE * HALO2)       // 2312
#define NSLOT     ((NELEM + 127) / 128)   // 19
#define HW        224
#define HW2       (HW * HW)
#define CO_TILE   8
#define NW        (CO_TILE * CI_TILE * 9) // 144 weight floats per stage

__device__ float g_buf1[102760448];
__device__ float g_buf2[102760448];

typedef unsigned long long u64;

__device__ __forceinline__ void fma2(u64& d, u64 a, u64 b)
{
    // packed 2xfp32 FMA: d.lo += a.lo*b.lo ; d.hi += a.hi*b.hi
    asm("fma.rn.f32x2 %0, %1, %2, %0;" : "+l"(d) : "l"(a), "l"(b));
}

template <int CIN>
__global__ __launch_bounds__(128, 3)
void conv3x3_pipe(const float* __restrict__ in,
                  const float* __restrict__ wgt,
                  float* __restrict__ out,
                  int Cout)
{
    __shared__ __align__(16) float  sA[2][NELEM];   // natural copy
    __shared__ __align__(16) float  sB[2][NELEM];   // shifted: sB[j] = v[j+1]
    __shared__ __align__(16) float2 sW[2][NW];      // duplicated weights

    const int tid = threadIdx.x;
    const int tx  = tid & 15;
    const int ty  = tid >> 4;
    const int cog = blockIdx.x;                  // co-group fastest -> L2 reuse
    const int bh  = blockIdx.y / 7;
    const int bw  = blockIdx.y - bh * 7;
    const int n   = blockIdx.z;
    const int hb  = bh * TILE, wb = bw * TILE;
    const int c0  = 2 * tx;                      // even -> aligned LDS.64
    const int r0  = 4 * ty;

    // ---- per-slot input offsets, computed ONCE (bounds folded in as -1) ----
    int goff[NSLOT];
#pragma unroll
    for (int k = 0; k < NSLOT; k++) {
        int idx = tid + 128 * k;
        int ciL = idx / HALO2;
        int rem = idx - ciL * HALO2;
        int r   = rem / HALO;
        int c   = rem - r * HALO;
        int gh  = hb - 1 + r, gw = wb - 1 + c;
        bool ok = (idx < NELEM) & ((unsigned)gh < HW) & ((unsigned)gw < HW);
        goff[k] = ok ? (ciL * HW2 + gh * HW + gw) : -1;
    }
    const bool tail = tid < (NELEM - 128 * (NSLOT - 1));   // last partial slot
    // sB write index for slot 0: idx==0 redirected to an unused cell
    const int sb0 = (tid == 0) ? (NELEM - 1) : (tid - 1);

    // ---- weight slot offsets (144 floats per stage; 128 + 16 threads) ----
    int wo0, wo1;
    {
        int idx = tid;
        int co = idx / (CI_TILE * 9); int rem = idx - co * (CI_TILE * 9);
        int ciL = rem / 9; int k = rem - ciL * 9;
        wo0 = ((cog * CO_TILE + co) * CIN + ciL) * 9 + k;
        idx = tid + 128;
        co = idx / (CI_TILE * 9); rem = idx - co * (CI_TILE * 9);
        ciL = rem / 9; k = rem - ciL * 9;
        wo1 = ((cog * CO_TILE + co) * CIN + ciL) * 9 + k;
    }
    const bool w2nd = (tid + 128) < NW;

    const float* src = in + (size_t)n * CIN * HW2;

    u64 acc[CO_TILE][4];
#pragma unroll
    for (int co = 0; co < CO_TILE; co++)
#pragma unroll
        for (int r = 0; r < 4; r++) acc[co][r] = 0ull;

    const int NSTAGE = CIN / CI_TILE;

    // ---- prologue: fill stage 0 directly ----
    {
#pragma unroll
        for (int k = 0; k < NSLOT; k++) {
            float v = 0.0f;
            if (goff[k] >= 0) v = __ldg(src + goff[k]);
            int idx = tid + 128 * k;
            if (k < NSLOT - 1 || tail) {
                sA[0][idx] = v;
                sB[0][(k == 0) ? sb0 : (idx - 1)] = v;
            }
        }
        float w0 = __ldg(wgt + wo0);
        sW[0][tid] = make_float2(w0, w0);
        if (w2nd) { float w1 = __ldg(wgt + wo1); sW[0][tid + 128] = make_float2(w1, w1); }
    }
    __syncthreads();

    for (int s = 0; s < NSTAGE; s++) {
        const int  cur  = s & 1;
        const int  nxt  = cur ^ 1;
        const bool more = (s + 1) < NSTAGE;

        // ---- prefetch stage s+1 into registers (latency hidden by compute) ----
        float v[NSLOT];
        float w0 = 0.0f, w1 = 0.0f;
        if (more) {
            const float* p = src + (size_t)(s + 1) * CI_TILE * HW2;
#pragma unroll
            for (int k = 0; k < NSLOT; k++) {
                v[k] = 0.0f;
                if (goff[k] >= 0) v[k] = __ldg(p + goff[k]);
            }
            w0 = __ldg(wgt + wo0 + (s + 1) * CI_TILE * 9);
            if (w2nd) w1 = __ldg(wgt + wo1 + (s + 1) * CI_TILE * 9);
        }

        // ---- compute stage s ----
        const float*  aBase = sA[cur];
        const float*  bBase = sB[cur];
        const float2* wBase = sW[cur];
#pragma unroll 1
        for (int ciL = 0; ciL < CI_TILE; ciL++) {
            u64 inp[6][3];
#pragma unroll
            for (int r = 0; r < 6; r++) {
                const float* pa = aBase + ciL * HALO2 + (r0 + r) * HALO + c0;
                const float* pb = bBase + ciL * HALO2 + (r0 + r) * HALO + c0;
                inp[r][0] = *reinterpret_cast<const u64*>(pa);
                inp[r][1] = *reinterpret_cast<const u64*>(pb);
                inp[r][2] = *reinterpret_cast<const u64*>(pa + 2);
            }
#pragma unroll
            for (int co = 0; co < CO_TILE; co++) {
#pragma unroll
                for (int kh = 0; kh < 3; kh++) {
#pragma unroll
                    for (int kw = 0; kw < 3; kw++) {
                        u64 wp = *reinterpret_cast<const u64*>(
                            &wBase[(co * CI_TILE + ciL) * 9 + kh * 3 + kw]);
#pragma unroll
                        for (int r2 = 0; r2 < 4; r2++)
                            fma2(acc[co][r2], inp[r2 + kh][kw], wp);
                    }
                }
            }
        }
        __syncthreads();   // everyone done reading buf[nxt] (stage s-1)

        // ---- publish stage s+1 ----
        if (more) {
#pragma unroll
            for (int k = 0; k < NSLOT; k++) {
                int idx = tid + 128 * k;
                if (k < NSLOT - 1 || tail) {
                    sA[nxt][idx] = v[k];
                    sB[nxt][(k == 0) ? sb0 : (idx - 1)] = v[k];
                }
            }
            sW[nxt][tid] = make_float2(w0, w0);
            if (w2nd) sW[nxt][tid + 128] = make_float2(w1, w1);
        }
        __syncthreads();
    }

    // ---- store: 64-bit stores of adjacent-column pairs ----
#pragma unroll
    for (int co = 0; co < CO_TILE; co++) {
#pragma unroll
        for (int r2 = 0; r2 < 4; r2++) {
            int h = hb + r0 + r2;
            float* p = out + (((size_t)n * Cout + cog * CO_TILE + co) * HW + h) * HW + wb + c0;
            *reinterpret_cast<u64*>(p) = acc[co][r2];
        }
    }
}

extern "C" void kernel_launch(void* const* d_in, const int* in_sizes, int n_in,
                              void* d_out, int out_size)
{
    const float* x  = (const float*)d_in[0];
    const float* w1 = (const float*)d_in[1];
    const float* w2 = (const float*)d_in[2];
    const float* w3 = (const float*)d_in[3];
    float* out = (float*)d_out;

    float* buf1 = nullptr;
    float* buf2 = nullptr;
    cudaGetSymbolAddress((void**)&buf1, g_buf1);
    cudaGetSymbolAddress((void**)&buf2, g_buf2);

    dim3 block(128);
    dim3 grid1(128 / CO_TILE, 7 * 7, 16);
    conv3x3_pipe<64><<<grid1, block>>>(x, w1, buf1, 128);
    dim3 grid2(128 / CO_TILE, 7 * 7, 16);
    conv3x3_pipe<128><<<grid2, block>>>(buf1, w2, buf2, 128);
    dim3 grid3(64 / CO_TILE, 7 * 7, 16);
    conv3x3_pipe<128><<<grid3, block>>>(buf2, w3, out, 64);
}

// round 3
// speedup vs baseline: 1.4397x; 1.0003x over previous
#include <cuda_runtime.h>

// ---------------------------------------------------------------------------
// 3x conv3x3 chain, fp32, NCHW, stride 1 pad 1. N=16, H=W=224, 64->128->128->64.
//
// Round 2: software-pipelined direct conv around packed fp32x2 FMA.
//  - Double-buffered smem (CI_TILE=2 channels per stage, 2 stages, ~39 KB).
//  - Register-staged prefetch: all next-stage LDGs issued BEFORE computing the
//    current stage; STS after barrier. DRAM latency hidden under 1152 cycles
//    of FMA2 work.
//  - Per-slot global offsets (bounds folded in as -1) computed ONCE before the
//    main loop -> no divisions / bounds math in the hot loop.
//  - Dual smem copies (natural + shifted-by-one) keep every 3x3 tap an aligned
//    LDS.64 pixel pair; weights duplicated (w,w) for broadcast LDS.64.
//  - Per thread: 8 co x 4 rows x 2 cols = 64 outputs in 32 packed accumulators.
// ---------------------------------------------------------------------------

#define TILE      32
#define CI_TILE   2
#define HALO      34
#define HALO2     1156
#define NELEM     (CI_TILE * HALO2)       // 2312
#define NSLOT     ((NELEM + 127) / 128)   // 19
#define HW        224
#define HW2       (HW * HW)
#define CO_TILE   8
#define NW        (CO_TILE * CI_TILE * 9) // 144 weight floats per stage

__device__ float g_buf1[102760448];
__device__ float g_buf2[102760448];

typedef unsigned long long u64;

__device__ __forceinline__ void fma2(u64& d, u64 a, u64 b)
{
    // packed 2xfp32 FMA: d.lo += a.lo*b.lo ; d.hi += a.hi*b.hi
    asm("fma.rn.f32x2 %0, %1, %2, %0;" : "+l"(d) : "l"(a), "l"(b));
}

template <int CIN>
__global__ __launch_bounds__(128, 3)
void conv3x3_pipe(const float* __restrict__ in,
                  const float* __restrict__ wgt,
                  float* __restrict__ out,
                  int Cout)
{
    __shared__ __align__(16) float  sA[2][NELEM];   // natural copy
    __shared__ __align__(16) float  sB[2][NELEM];   // shifted: sB[j] = v[j+1]
    __shared__ __align__(16) float2 sW[2][NW];      // duplicated weights

    const int tid = threadIdx.x;
    const int tx  = tid & 15;
    const int ty  = tid >> 4;
    const int cog = blockIdx.x;                  // co-group fastest -> L2 reuse
    const int bh  = blockIdx.y / 7;
    const int bw  = blockIdx.y - bh * 7;
    const int n   = blockIdx.z;
    const int hb  = bh * TILE, wb = bw * TILE;
    const int c0  = 2 * tx;                      // even -> aligned LDS.64
    const int r0  = 4 * ty;

    // ---- per-slot input offsets, computed ONCE (bounds folded in as -1) ----
    int goff[NSLOT];
#pragma unroll
    for (int k = 0; k < NSLOT; k++) {
        int idx = tid + 128 * k;
        int ciL = idx / HALO2;
        int rem = idx - ciL * HALO2;
        int r   = rem / HALO;
        int c   = rem - r * HALO;
        int gh  = hb - 1 + r, gw = wb - 1 + c;
        bool ok = (idx < NELEM) & ((unsigned)gh < HW) & ((unsigned)gw < HW);
        goff[k] = ok ? (ciL * HW2 + gh * HW + gw) : -1;
    }
    const bool tail = tid < (NELEM - 128 * (NSLOT - 1));   // last partial slot
    // sB write index for slot 0: idx==0 redirected to an unused cell
    const int sb0 = (tid == 0) ? (NELEM - 1) : (tid - 1);

    // ---- weight slot offsets (144 floats per stage; 128 + 16 threads) ----
    int wo0, wo1;
    {
        int idx = tid;
        int co = idx / (CI_TILE * 9); int rem = idx - co * (CI_TILE * 9);
        int ciL = rem / 9; int k = rem - ciL * 9;
        wo0 = ((cog * CO_TILE + co) * CIN + ciL) * 9 + k;
        idx = tid + 128;
        co = idx / (CI_TILE * 9); rem = idx - co * (CI_TILE * 9);
        ciL = rem / 9; k = rem - ciL * 9;
        wo1 = ((cog * CO_TILE + co) * CIN + ciL) * 9 + k;
    }
    const bool w2nd = (tid + 128) < NW;

    const float* src = in + (size_t)n * CIN * HW2;

    u64 acc[CO_TILE][4];
#pragma unroll
    for (int co = 0; co < CO_TILE; co++)
#pragma unroll
        for (int r = 0; r < 4; r++) acc[co][r] = 0ull;

    const int NSTAGE = CIN / CI_TILE;

    // ---- prologue: fill stage 0 directly ----
    {
#pragma unroll
        for (int k = 0; k < NSLOT; k++) {
            float v = 0.0f;
            if (goff[k] >= 0) v = __ldg(src + goff[k]);
            int idx = tid + 128 * k;
            if (k < NSLOT - 1 || tail) {
                sA[0][idx] = v;
                sB[0][(k == 0) ? sb0 : (idx - 1)] = v;
            }
        }
        float w0 = __ldg(wgt + wo0);
        sW[0][tid] = make_float2(w0, w0);
        if (w2nd) { float w1 = __ldg(wgt + wo1); sW[0][tid + 128] = make_float2(w1, w1); }
    }
    __syncthreads();

    for (int s = 0; s < NSTAGE; s++) {
        const int  cur  = s & 1;
        const int  nxt  = cur ^ 1;
        const bool more = (s + 1) < NSTAGE;

        // ---- prefetch stage s+1 into registers (latency hidden by compute) ----
        float v[NSLOT];
        float w0 = 0.0f, w1 = 0.0f;
        if (more) {
            const float* p = src + (size_t)(s + 1) * CI_TILE * HW2;
#pragma unroll
            for (int k = 0; k < NSLOT; k++) {
                v[k] = 0.0f;
                if (goff[k] >= 0) v[k] = __ldg(p + goff[k]);
            }
            w0 = __ldg(wgt + wo0 + (s + 1) * CI_TILE * 9);
            if (w2nd) w1 = __ldg(wgt + wo1 + (s + 1) * CI_TILE * 9);
        }

        // ---- compute stage s ----
        const float*  aBase = sA[cur];
        const float*  bBase = sB[cur];
        const float2* wBase = sW[cur];
#pragma unroll 1
        for (int ciL = 0; ciL < CI_TILE; ciL++) {
            u64 inp[6][3];
#pragma unroll
            for (int r = 0; r < 6; r++) {
                const float* pa = aBase + ciL * HALO2 + (r0 + r) * HALO + c0;
                const float* pb = bBase + ciL * HALO2 + (r0 + r) * HALO + c0;
                inp[r][0] = *reinterpret_cast<const u64*>(pa);
                inp[r][1] = *reinterpret_cast<const u64*>(pb);
                inp[r][2] = *reinterpret_cast<const u64*>(pa + 2);
            }
#pragma unroll
            for (int co = 0; co < CO_TILE; co++) {
#pragma unroll
                for (int kh = 0; kh < 3; kh++) {
#pragma unroll
                    for (int kw = 0; kw < 3; kw++) {
                        u64 wp = *reinterpret_cast<const u64*>(
                            &wBase[(co * CI_TILE + ciL) * 9 + kh * 3 + kw]);
#pragma unroll
                        for (int r2 = 0; r2 < 4; r2++)
                            fma2(acc[co][r2], inp[r2 + kh][kw], wp);
                    }
                }
            }
        }
        __syncthreads();   // everyone done reading buf[nxt] (stage s-1)

        // ---- publish stage s+1 ----
        if (more) {
#pragma unroll
            for (int k = 0; k < NSLOT; k++) {
                int idx = tid + 128 * k;
                if (k < NSLOT - 1 || tail) {
                    sA[nxt][idx] = v[k];
                    sB[nxt][(k == 0) ? sb0 : (idx - 1)] = v[k];
                }
            }
            sW[nxt][tid] = make_float2(w0, w0);
            if (w2nd) sW[nxt][tid + 128] = make_float2(w1, w1);
        }
        __syncthreads();
    }

    // ---- store: 64-bit stores of adjacent-column pairs ----
#pragma unroll
    for (int co = 0; co < CO_TILE; co++) {
#pragma unroll
        for (int r2 = 0; r2 < 4; r2++) {
            int h = hb + r0 + r2;
            float* p = out + (((size_t)n * Cout + cog * CO_TILE + co) * HW + h) * HW + wb + c0;
            *reinterpret_cast<u64*>(p) = acc[co][r2];
        }
    }
}

extern "C" void kernel_launch(void* const* d_in, const int* in_sizes, int n_in,
                              void* d_out, int out_size)
{
    const float* x  = (const float*)d_in[0];
    const float* w1 = (const float*)d_in[1];
    const float* w2 = (const float*)d_in[2];
    const float* w3 = (const float*)d_in[3];
    float* out = (float*)d_out;

    float* buf1 = nullptr;
    float* buf2 = nullptr;
    cudaGetSymbolAddress((void**)&buf1, g_buf1);
    cudaGetSymbolAddress((void**)&buf2, g_buf2);

    dim3 block(128);
    dim3 grid1(128 / CO_TILE, 7 * 7, 16);
    conv3x3_pipe<64><<<grid1, block>>>(x, w1, buf1, 128);
    dim3 grid2(128 / CO_TILE, 7 * 7, 16);
    conv3x3_pipe<128><<<grid2, block>>>(buf1, w2, buf2, 128);
    dim3 grid3(64 / CO_TILE, 7 * 7, 16);
    conv3x3_pipe<128><<<grid3, block>>>(buf2, w3, out, 64);
}

// round 4
// speedup vs baseline: 1.4403x; 1.0004x over previous
#include <cuda_runtime.h>

// ---------------------------------------------------------------------------
// 3x conv3x3 chain, fp32, NCHW, stride 1 pad 1. N=16, H=W=224, 64->128->128->64.
//
// Round 2: software-pipelined direct conv around packed fp32x2 FMA.
//  - Double-buffered smem (CI_TILE=2 channels per stage, 2 stages, ~39 KB).
//  - Register-staged prefetch: all next-stage LDGs issued BEFORE computing the
//    current stage; STS after barrier. DRAM latency hidden under 1152 cycles
//    of FMA2 work.
//  - Per-slot global offsets (bounds folded in as -1) computed ONCE before the
//    main loop -> no divisions / bounds math in the hot loop.
//  - Dual smem copies (natural + shifted-by-one) keep every 3x3 tap an aligned
//    LDS.64 pixel pair; weights duplicated (w,w) for broadcast LDS.64.
//  - Per thread: 8 co x 4 rows x 2 cols = 64 outputs in 32 packed accumulators.
// ---------------------------------------------------------------------------

#define TILE      32
#define CI_TILE   2
#define HALO      34
#define HALO2     1156
#define NELEM     (CI_TILE * HALO2)       // 2312
#define NSLOT     ((NELEM + 127) / 128)   // 19
#define HW        224
#define HW2       (HW * HW)
#define CO_TILE   8
#define NW        (CO_TILE * CI_TILE * 9) // 144 weight floats per stage

__device__ float g_buf1[102760448];
__device__ float g_buf2[102760448];

typedef unsigned long long u64;

__device__ __forceinline__ void fma2(u64& d, u64 a, u64 b)
{
    // packed 2xfp32 FMA: d.lo += a.lo*b.lo ; d.hi += a.hi*b.hi
    asm("fma.rn.f32x2 %0, %1, %2, %0;" : "+l"(d) : "l"(a), "l"(b));
}

template <int CIN>
__global__ __launch_bounds__(128, 3)
void conv3x3_pipe(const float* __restrict__ in,
                  const float* __restrict__ wgt,
                  float* __restrict__ out,
                  int Cout)
{
    __shared__ __align__(16) float  sA[2][NELEM];   // natural copy
    __shared__ __align__(16) float  sB[2][NELEM];   // shifted: sB[j] = v[j+1]
    __shared__ __align__(16) float2 sW[2][NW];      // duplicated weights

    const int tid = threadIdx.x;
    const int tx  = tid & 15;
    const int ty  = tid >> 4;
    const int cog = blockIdx.x;                  // co-group fastest -> L2 reuse
    const int bh  = blockIdx.y / 7;
    const int bw  = blockIdx.y - bh * 7;
    const int n   = blockIdx.z;
    const int hb  = bh * TILE, wb = bw * TILE;
    const int c0  = 2 * tx;                      // even -> aligned LDS.64
    const int r0  = 4 * ty;

    // ---- per-slot input offsets, computed ONCE (bounds folded in as -1) ----
    int goff[NSLOT];
#pragma unroll
    for (int k = 0; k < NSLOT; k++) {
        int idx = tid + 128 * k;
        int ciL = idx / HALO2;
        int rem = idx - ciL * HALO2;
        int r   = rem / HALO;
        int c   = rem - r * HALO;
        int gh  = hb - 1 + r, gw = wb - 1 + c;
        bool ok = (idx < NELEM) & ((unsigned)gh < HW) & ((unsigned)gw < HW);
        goff[k] = ok ? (ciL * HW2 + gh * HW + gw) : -1;
    }
    const bool tail = tid < (NELEM - 128 * (NSLOT - 1));   // last partial slot
    // sB write index for slot 0: idx==0 redirected to an unused cell
    const int sb0 = (tid == 0) ? (NELEM - 1) : (tid - 1);

    // ---- weight slot offsets (144 floats per stage; 128 + 16 threads) ----
    int wo0, wo1;
    {
        int idx = tid;
        int co = idx / (CI_TILE * 9); int rem = idx - co * (CI_TILE * 9);
        int ciL = rem / 9; int k = rem - ciL * 9;
        wo0 = ((cog * CO_TILE + co) * CIN + ciL) * 9 + k;
        idx = tid + 128;
        co = idx / (CI_TILE * 9); rem = idx - co * (CI_TILE * 9);
        ciL = rem / 9; k = rem - ciL * 9;
        wo1 = ((cog * CO_TILE + co) * CIN + ciL) * 9 + k;
    }
    const bool w2nd = (tid + 128) < NW;

    const float* src = in + (size_t)n * CIN * HW2;

    u64 acc[CO_TILE][4];
#pragma unroll
    for (int co = 0; co < CO_TILE; co++)
#pragma unroll
        for (int r = 0; r < 4; r++) acc[co][r] = 0ull;

    const int NSTAGE = CIN / CI_TILE;

    // ---- prologue: fill stage 0 directly ----
    {
#pragma unroll
        for (int k = 0; k < NSLOT; k++) {
            float v = 0.0f;
            if (goff[k] >= 0) v = __ldg(src + goff[k]);
            int idx = tid + 128 * k;
            if (k < NSLOT - 1 || tail) {
                sA[0][idx] = v;
                sB[0][(k == 0) ? sb0 : (idx - 1)] = v;
            }
        }
        float w0 = __ldg(wgt + wo0);
        sW[0][tid] = make_float2(w0, w0);
        if (w2nd) { float w1 = __ldg(wgt + wo1); sW[0][tid + 128] = make_float2(w1, w1); }
    }
    __syncthreads();

    for (int s = 0; s < NSTAGE; s++) {
        const int  cur  = s & 1;
        const int  nxt  = cur ^ 1;
        const bool more = (s + 1) < NSTAGE;

        // ---- prefetch stage s+1 into registers (latency hidden by compute) ----
        float v[NSLOT];
        float w0 = 0.0f, w1 = 0.0f;
        if (more) {
            const float* p = src + (size_t)(s + 1) * CI_TILE * HW2;
#pragma unroll
            for (int k = 0; k < NSLOT; k++) {
                v[k] = 0.0f;
                if (goff[k] >= 0) v[k] = __ldg(p + goff[k]);
            }
            w0 = __ldg(wgt + wo0 + (s + 1) * CI_TILE * 9);
            if (w2nd) w1 = __ldg(wgt + wo1 + (s + 1) * CI_TILE * 9);
        }

        // ---- compute stage s ----
        const float*  aBase = sA[cur];
        const float*  bBase = sB[cur];
        const float2* wBase = sW[cur];
#pragma unroll 1
        for (int ciL = 0; ciL < CI_TILE; ciL++) {
            u64 inp[6][3];
#pragma unroll
            for (int r = 0; r < 6; r++) {
                const float* pa = aBase + ciL * HALO2 + (r0 + r) * HALO + c0;
                const float* pb = bBase + ciL * HALO2 + (r0 + r) * HALO + c0;
                inp[r][0] = *reinterpret_cast<const u64*>(pa);
                inp[r][1] = *reinterpret_cast<const u64*>(pb);
                inp[r][2] = *reinterpret_cast<const u64*>(pa + 2);
            }
#pragma unroll
            for (int co = 0; co < CO_TILE; co++) {
#pragma unroll
                for (int kh = 0; kh < 3; kh++) {
#pragma unroll
                    for (int kw = 0; kw < 3; kw++) {
                        u64 wp = *reinterpret_cast<const u64*>(
                            &wBase[(co * CI_TILE + ciL) * 9 + kh * 3 + kw]);
#pragma unroll
                        for (int r2 = 0; r2 < 4; r2++)
                            fma2(acc[co][r2], inp[r2 + kh][kw], wp);
                    }
                }
            }
        }
        __syncthreads();   // everyone done reading buf[nxt] (stage s-1)

        // ---- publish stage s+1 ----
        if (more) {
#pragma unroll
            for (int k = 0; k < NSLOT; k++) {
                int idx = tid + 128 * k;
                if (k < NSLOT - 1 || tail) {
                    sA[nxt][idx] = v[k];
                    sB[nxt][(k == 0) ? sb0 : (idx - 1)] = v[k];
                }
            }
            sW[nxt][tid] = make_float2(w0, w0);
            if (w2nd) sW[nxt][tid + 128] = make_float2(w1, w1);
        }
        __syncthreads();
    }

    // ---- store: 64-bit stores of adjacent-column pairs ----
#pragma unroll
    for (int co = 0; co < CO_TILE; co++) {
#pragma unroll
        for (int r2 = 0; r2 < 4; r2++) {
            int h = hb + r0 + r2;
            float* p = out + (((size_t)n * Cout + cog * CO_TILE + co) * HW + h) * HW + wb + c0;
            *reinterpret_cast<u64*>(p) = acc[co][r2];
        }
    }
}

extern "C" void kernel_launch(void* const* d_in, const int* in_sizes, int n_in,
                              void* d_out, int out_size)
{
    const float* x  = (const float*)d_in[0];
    const float* w1 = (const float*)d_in[1];
    const float* w2 = (const float*)d_in[2];
    const float* w3 = (const float*)d_in[3];
    float* out = (float*)d_out;

    float* buf1 = nullptr;
    float* buf2 = nullptr;
    cudaGetSymbolAddress((void**)&buf1, g_buf1);
    cudaGetSymbolAddress((void**)&buf2, g_buf2);

    dim3 block(128);
    dim3 grid1(128 / CO_TILE, 7 * 7, 16);
    conv3x3_pipe<64><<<grid1, block>>>(x, w1, buf1, 128);
    dim3 grid2(128 / CO_TILE, 7 * 7, 16);
    conv3x3_pipe<128><<<grid2, block>>>(buf1, w2, buf2, 128);
    dim3 grid3(64 / CO_TILE, 7 * 7, 16);
    conv3x3_pipe<128><<<grid3, block>>>(buf2, w3, out, 64);
}